// round 15
// baseline (speedup 1.0000x reference)
#include <cuda_runtime.h>
#include <cstddef>
#include <math.h>

#define T_ 4
#define B_ 16
#define C_ 256
#define N_ 512
#define H_ 1024
#define BK 8      // dense GEMM k-tile
#define KC 32     // sparse kernel c-chunk
#define G_ 16     // sparse kernel n-columns per CTA

// ---------------- scratch (device globals; no allocation allowed) ----------
__device__ __align__(16) float g_qs[(size_t)T_*B_*C_*N_];
__device__ __align__(16) float g_ks[(size_t)T_*B_*C_*N_];
__device__ __align__(16) float g_vs[(size_t)T_*B_*C_*N_];
__device__ __align__(16) float g_rs[(size_t)T_*B_*C_*N_];
__device__ __align__(16) float g_x1[(size_t)T_*B_*C_*N_];
__device__ __align__(16) float g_h [(size_t)T_*B_*H_*N_];

// transposed weights for sparse layers: WT[c*O + o] = W[o*Cin + c]
__device__ __align__(16) float g_wtp[(size_t)C_*C_];   // proj
__device__ __align__(16) float g_wt2[(size_t)C_*H_];   // fc2

__device__ __forceinline__ float* buf_ptr(int id){
  switch(id){
    case 0: return g_qs; case 1: return g_ks; case 2: return g_vs;
    case 3: return g_rs; case 4: return g_x1; default: return g_h;
  }
}
__device__ __forceinline__ float* wt_ptr(int id){
  return (id == 3) ? g_wtp : g_wt2;
}

// ---------------- packed f32x2 helpers (bit-exact per-lane IEEE ops) -------
__device__ __forceinline__ unsigned long long pk2(float v){
  unsigned long long r; unsigned u = __float_as_uint(v);
  asm("mov.b64 %0, {%1, %1};" : "=l"(r) : "r"(u));
  return r;
}
__device__ __forceinline__ void fma2(unsigned long long &d,
                                     unsigned long long a, unsigned long long b){
  asm("fma.rn.f32x2 %0, %1, %2, %0;" : "+l"(d) : "l"(a), "l"(b));
}
__device__ __forceinline__ void fadd2(unsigned long long &d, unsigned long long a){
  asm("add.rn.f32x2 %0, %0, %1;" : "+l"(d) : "l"(a));
}
__device__ __forceinline__ float2 unpk(unsigned long long p){
  unsigned lo, hi;
  asm("mov.b64 {%0, %1}, %2;" : "=r"(lo), "=r"(hi) : "l"(p));
  return make_float2(__uint_as_float(lo), __uint_as_float(hi));
}

// ---------------- cp.async helpers ----------------------------------------
__device__ __forceinline__ void cpa16(void* smem_dst, const void* gmem_src){
  unsigned d = (unsigned)__cvta_generic_to_shared(smem_dst);
  asm volatile("cp.async.cg.shared.global [%0], [%1], 16;" :: "r"(d), "l"(gmem_src));
}
#define CPA_COMMIT()   asm volatile("cp.async.commit_group;")
#define CPA_WAIT_ALL() asm volatile("cp.async.wait_group 0;" ::: "memory")

// ------------- prep: transpose weights (device-side destination!) ----------
__global__ void prep_wt(const float* __restrict__ W, int wid, int O, int Cin){
  float* WT = wt_ptr(wid);
  int i = blockIdx.x * blockDim.x + threadIdx.x;
  int tot = O * Cin;
  for (; i < tot; i += gridDim.x * blockDim.x){
    int c = i / O, o = i % O;
    WT[i] = W[(size_t)o * Cin + c];
  }
}

// ================= DENSE path (verbatim R11 best: 1247us) ==================
// fused GEMM + (reference-order) BN + LIF scan over T. Serial ascending-c
// fp32 fma per output; FFMA2 pairs ADJACENT O-ROWS -> bit-exact.
// Block tile 128(o) x 32(n) x 4(t), 128 threads, micro 16x2x4.
#define XROW 320
__device__ __forceinline__ void gemm_lif_body(
    const float* __restrict__ X, float* __restrict__ out,
    const float* __restrict__ res,
    const float* __restrict__ W, const float* __restrict__ bn,
    const float* __restrict__ bias, int Cin, int Cout,
    int b, int o0, int n0)
{
  __shared__ __align__(16) float sW [2][BK][128];
  __shared__ __align__(16) float sX2[2][BK][XROW];
  __shared__ float sBN[4][128];

  const int tid = threadIdx.x;
  const int to = tid >> 4;
  const int tn = tid & 15;
  const int xk = tid >> 4;
  const int xt = (tid >> 2) & 3;
  const int xq = tid & 3;

  {
    const int o = o0 + tid;
    sBN[0][tid] = bn[o] / sqrtf(bn[3*Cout + o] + 1e-5f);
    sBN[1][tid] = bn[2*Cout + o];
    sBN[2][tid] = bn[Cout + o];
    sBN[3][tid] = bias ? bias[o] : 0.0f;
  }

  float4 rw0, rw1, rx0, rx1;
  auto load_regs = [&](int kk){
    const float* wp = W + (size_t)(o0 + tid) * Cin + kk;
    rw0 = *(const float4*)(wp);
    rw1 = *(const float4*)(wp + 4);
    const float* xp = X + ((size_t)(xt*B_ + b) * Cin + kk + xk) * N_ + n0;
    rx0 = *(const float4*)(xp + xq*4);
    rx1 = *(const float4*)(xp + xq*4 + 16);
  };
  auto sts_regs = [&](int s){
    sW[s][0][tid] = rw0.x; sW[s][1][tid] = rw0.y;
    sW[s][2][tid] = rw0.z; sW[s][3][tid] = rw0.w;
    sW[s][4][tid] = rw1.x; sW[s][5][tid] = rw1.y;
    sW[s][6][tid] = rw1.z; sW[s][7][tid] = rw1.w;
    float xv0[4] = {rx0.x, rx0.y, rx0.z, rx0.w};
    float xv1[4] = {rx1.x, rx1.y, rx1.z, rx1.w};
#pragma unroll
    for (int i=0;i<4;i++){
      const int nl = xq*4 + i;
      const int col = (nl>>1)*20 + (nl&1)*8 + xt*2;
      *(unsigned long long*)&sX2[s][xk][col] = pk2(xv0[i]);
    }
#pragma unroll
    for (int i=0;i<4;i++){
      const int nl = xq*4 + 16 + i;
      const int col = (nl>>1)*20 + (nl&1)*8 + xt*2;
      *(unsigned long long*)&sX2[s][xk][col] = pk2(xv1[i]);
    }
  };

  unsigned long long accp[8][8];
#pragma unroll
  for (int i=0;i<8;i++)
#pragma unroll
    for (int j=0;j<8;j++) accp[i][j] = 0ULL;

  auto compute = [&](int s){
#pragma unroll
    for (int k = 0; k < BK; k++){
      const float* wp = &sW[s][k][to*16];
      ulonglong2 w01 = *(const ulonglong2*)(wp);
      ulonglong2 w23 = *(const ulonglong2*)(wp + 4);
      ulonglong2 w45 = *(const ulonglong2*)(wp + 8);
      ulonglong2 w67 = *(const ulonglong2*)(wp + 12);
      unsigned long long ap[8] = {w01.x,w01.y,w23.x,w23.y,
                                  w45.x,w45.y,w67.x,w67.y};
      const float* bp = &sX2[s][k][tn*20];
      ulonglong2 q0 = *(const ulonglong2*)(bp);
      ulonglong2 q1 = *(const ulonglong2*)(bp + 4);
      ulonglong2 q2 = *(const ulonglong2*)(bp + 8);
      ulonglong2 q3 = *(const ulonglong2*)(bp + 12);
      unsigned long long pb[8] = {q0.x,q0.y,q1.x,q1.y,q2.x,q2.y,q3.x,q3.y};
#pragma unroll
      for (int j=0; j<8; j++){
#pragma unroll
        for (int p=0; p<8; p++) fma2(accp[p][j], ap[p], pb[j]);
      }
    }
  };

  const int ntile = Cin / BK;
  load_regs(0);

#pragma unroll 1
  for (int it = 0; it < ntile; it += 2){
    sts_regs(0);
    __syncthreads();
    load_regs((it + 1) * BK);
    compute(0);
    sts_regs(1);
    __syncthreads();
    if (it + 2 < ntile) load_regs((it + 2) * BK);
    compute(1);
  }

#pragma unroll
  for (int p=0; p<8; p++) {
    float accs[2][8];
#pragma unroll
    for (int j=0;j<8;j++){
      float2 pr = unpk(accp[p][j]);
      accs[0][j] = pr.x; accs[1][j] = pr.y;
    }
#pragma unroll
    for (int h2=0; h2<2; h2++) {
      const int oloc = to*16 + 2*p + h2;
      const int o = o0 + oloc;
      const float s_  = sBN[0][oloc];
      const float m_  = sBN[1][oloc];
      const float be_ = sBN[2][oloc];
      const float bc_ = sBN[3][oloc];
#pragma unroll
      for (int n=0; n<2; n++) {
        float mem = 0.0f;
        float sp[4];
#pragma unroll
        for (int t=0; t<4; t++) {
          float ypre = accs[h2][n*4 + t] + bc_;
          float y    = fmaf(ypre - m_, s_, be_);
          float m2   = mem + (y - mem) * 0.5f;
          bool fire  = (m2 > 0.5f);
          mem = fire ? 0.0f : m2;
          sp[t] = fire ? 1.0f : 0.0f;
        }
#pragma unroll
        for (int t=0; t<4; t++) {
          const size_t idx = ((size_t)(t*B_ + b) * Cout + o) * N_ + n0 + tn*2 + n;
          float v = sp[t];
          if (res) v += res[idx];
          out[idx] = v;
        }
      }
    }
  }
}

__global__ __launch_bounds__(128, 2)
void qkv_gemm_kernel(const float* __restrict__ x,
                     const float* __restrict__ Wq, const float* __restrict__ bnq,
                     const float* __restrict__ Wk, const float* __restrict__ bnk,
                     const float* __restrict__ Wv, const float* __restrict__ bnv)
{
  const int gy = blockIdx.y;
  const int gemm = gy >> 1;
  const int o0 = (gy & 1) * 128;
  const float* W  = (gemm == 0) ? Wq  : (gemm == 1) ? Wk  : Wv;
  const float* bn = (gemm == 0) ? bnq : (gemm == 1) ? bnk : bnv;
  float* out = buf_ptr(gemm);
  gemm_lif_body(x, out, nullptr, W, bn, nullptr, C_, C_,
                blockIdx.z, o0, blockIdx.x * 32);
}

__global__ __launch_bounds__(128, 2)
void gemm_lif_kernel(const float* __restrict__ Xext, float* __restrict__ outext,
                     const float* __restrict__ resext,
                     int xid, int oid, int rid,
                     const float* __restrict__ W, const float* __restrict__ bn,
                     const float* __restrict__ bias, int Cin, int Cout)
{
  const float* X   = (xid >= 0) ? buf_ptr(xid) : Xext;
  float* out       = (oid >= 0) ? buf_ptr(oid) : outext;
  const float* res = (rid == -2) ? nullptr : ((rid >= 0) ? buf_ptr(rid) : resext);
  gemm_lif_body(X, out, res, W, bn, bias, Cin, Cout,
                blockIdx.z, blockIdx.y * 128, blockIdx.x * 32);
}

// ================= SPARSE path (binary-spike input layers) =================
// y[o,n,t] = sum over ACTIVE c (ascending) of W[o,c]  — bit-exact vs dense:
// skipped terms are exact fmaf(w, 0, acc) = acc (acc never -0).
// CTA: one b, G_=16 n-columns, all 256 o, all 4 t. Threads own o-pairs.
// W streamed from WT [c][o] via cp.async double-buffered KC=32 chunks.
struct SparseSmem {
  float    sWc[2][KC][256];       // 64KB
  unsigned smask[G_][4][32];      // 8KB  (bit c%32 of word c/32, per (g,t))
  float    sBN[4][256];           // 4KB
};

__global__ __launch_bounds__(128, 2)
void spike_gemm_lif_kernel(const float* __restrict__ resext,
                           float* __restrict__ outext,
                           int sid, int oid, int rid, int wid,
                           const float* __restrict__ bn,
                           const float* __restrict__ bias, int Cin)
{
  extern __shared__ __align__(16) unsigned char sp_raw[];
  SparseSmem* sm = reinterpret_cast<SparseSmem*>(sp_raw);

  const int tid = threadIdx.x;
  const int lane = tid & 31, warp = tid >> 5;
  const int b  = blockIdx.z;
  const int n0 = blockIdx.x * G_;
  const int Cout = 256;

  const float* S   = buf_ptr(sid);
  float* out       = (oid >= 0) ? buf_ptr(oid) : outext;
  const float* res = (rid >= 0) ? buf_ptr(rid) : resext;
  const float* WT  = wt_ptr(wid);

  // BN params (256 o)
  for (int o = tid; o < 256; o += 128){
    sm->sBN[0][o] = bn[o] / sqrtf(bn[3*Cout + o] + 1e-5f);
    sm->sBN[1][o] = bn[2*Cout + o];
    sm->sBN[2][o] = bn[Cout + o];
    sm->sBN[3][o] = bias ? bias[o] : 0.0f;
  }

  // build activity bitmasks: thread reads 16 n-floats for its (t, c)
#pragma unroll 1
  for (int t = 0; t < 4; t++){
#pragma unroll 1
    for (int cb = 0; cb < Cin/128; cb++){
      const int c = cb*128 + tid;
      const float* spp = S + ((size_t)(t*B_ + b)*Cin + c)*N_ + n0;
      float4 v0 = *(const float4*)(spp);
      float4 v1 = *(const float4*)(spp + 4);
      float4 v2 = *(const float4*)(spp + 8);
      float4 v3 = *(const float4*)(spp + 12);
      float vv[16] = {v0.x,v0.y,v0.z,v0.w, v1.x,v1.y,v1.z,v1.w,
                      v2.x,v2.y,v2.z,v2.w, v3.x,v3.y,v3.z,v3.w};
      const int word = cb*4 + warp;   // c = word*32 + lane
#pragma unroll
      for (int g = 0; g < G_; g++){
        unsigned m = __ballot_sync(0xffffffffu, vv[g] != 0.0f);
        if (lane == 0) sm->smask[g][t][word] = m;
      }
    }
  }
  __syncthreads();

  // accumulators: o-pair (2*tid, 2*tid+1) packed, per (g, t)
  unsigned long long acc[G_][4];
#pragma unroll
  for (int g=0; g<G_; g++)
#pragma unroll
    for (int t=0; t<4; t++) acc[g][t] = 0ULL;

  // W chunk loader: sWc[buf][c_local][o] <- WT[(kc*KC + c_local)*256 + o]
  auto cpa_w = [&](int buf, int kc){
#pragma unroll
    for (int i=0;i<16;i++){
      const int idx = i*128 + tid;          // 0..2047
      const int row = idx >> 6;             // 0..31
      const int col = (idx & 63) * 4;       // float offset 0..252
      cpa16(&sm->sWc[buf][row][col], WT + (size_t)(kc*KC + row)*256 + col);
    }
  };

  const int nchunk = Cin / KC;
  cpa_w(0, 0); CPA_COMMIT();

#pragma unroll 1
  for (int kc = 0; kc < nchunk; kc++){
    const int buf = kc & 1;
    CPA_WAIT_ALL();
    __syncthreads();
    if (kc + 1 < nchunk){ cpa_w(1 - buf, kc + 1); CPA_COMMIT(); }
    // sparse adds: ascending c within chunk (ffs = lowest bit first)
#pragma unroll
    for (int g=0; g<G_; g++){
#pragma unroll
      for (int t=0; t<4; t++){
        unsigned m = sm->smask[g][t][kc];
        while (m){
          const int bit = __ffs(m) - 1;
          m &= m - 1;
          unsigned long long w =
            *(const unsigned long long*)&sm->sWc[buf][bit][tid*2];
          fadd2(acc[g][t], w);
        }
      }
    }
    __syncthreads();   // adds on buf done before it is refilled at kc+2
  }

  // epilogue: bias -> BN -> LIF over t -> +residual ; float4 writes along n
#pragma unroll
  for (int g4 = 0; g4 < G_/4; g4++){
#pragma unroll
    for (int h = 0; h < 2; h++){
      const int o = tid*2 + h;
      const float s_  = sm->sBN[0][o];
      const float m_  = sm->sBN[1][o];
      const float be_ = sm->sBN[2][o];
      const float bc_ = sm->sBN[3][o];
      float spv[4][4];   // [t][gg]
#pragma unroll
      for (int gg = 0; gg < 4; gg++){
        const int g = g4*4 + gg;
        float mem = 0.0f;
#pragma unroll
        for (int t=0; t<4; t++){
          float2 pr = unpk(acc[g][t]);
          float ypre = (h ? pr.y : pr.x) + bc_;
          float y    = fmaf(ypre - m_, s_, be_);
          float m2   = mem + (y - mem) * 0.5f;
          bool fire  = (m2 > 0.5f);
          mem = fire ? 0.0f : m2;
          spv[t][gg] = fire ? 1.0f : 0.0f;
        }
      }
#pragma unroll
      for (int t=0; t<4; t++){
        const size_t idx = ((size_t)(t*B_ + b)*256 + o)*N_ + n0 + g4*4;
        float4 rr = *(const float4*)(res + idx);
        float4 ov;
        ov.x = spv[t][0] + rr.x;
        ov.y = spv[t][1] + rr.y;
        ov.z = spv[t][2] + rr.z;
        ov.w = spv[t][3] + rr.w;
        *(float4*)(out + idx) = ov;
      }
    }
  }
}

// ------------- spiking linear attention + attn-LIF (bit-exact integer math)
__global__ __launch_bounds__(256)
void attn_lif_kernel()
{
  __shared__ unsigned kb[16][17], vb[16][17];
  __shared__ float sKV[16][17];
  const int b = blockIdx.x;
  const int h = blockIdx.y;
  const int tid = threadIdx.x;
  const int warp = tid >> 5, lane = tid & 31;
  const int d1 = tid >> 4, d2 = tid & 15;

  float mem[2][16];
#pragma unroll
  for (int j=0;j<2;j++)
#pragma unroll
    for (int d=0; d<16; d++) mem[j][d] = 0.0f;

#pragma unroll 1
  for (int t=0; t<T_; t++){
    const size_t base = ((size_t)(t*B_ + b) * C_ + h*16) * N_;
    __syncthreads();

#pragma unroll 4
    for (int i = 0; i < 32; i++){
      const int idx = warp * 32 + i;
      const int row = idx >> 4, word = idx & 15;
      const size_t off = base + (size_t)row * N_ + word * 32 + lane;
      unsigned uk = __ballot_sync(0xffffffffu, g_ks[off] != 0.0f);
      unsigned uv = __ballot_sync(0xffffffffu, g_vs[off] != 0.0f);
      if (lane == 0){ kb[row][word] = uk; vb[row][word] = uv; }
    }
    __syncthreads();

    {
      int kv = 0;
#pragma unroll
      for (int w=0; w<16; w++) kv += __popc(kb[d1][w] & vb[d2][w]);
      sKV[d1][d2] = (float)kv;
    }
    __syncthreads();

#pragma unroll
    for (int half=0; half<2; half++){
      const int n = tid + half*256;
      float qv[16];
#pragma unroll
      for (int dd=0; dd<16; dd++) qv[dd] = g_qs[base + (size_t)dd*N_ + n];
#pragma unroll
      for (int d=0; d<16; d++){
        float r = 0.0f;
#pragma unroll
        for (int dd=0; dd<16; dd++) r = fmaf(qv[dd], sKV[dd][d], r);
        r *= 0.0625f;
        float m2 = mem[half][d] + (r - mem[half][d]) * 0.5f;
        bool fire = (m2 > 0.5f);
        mem[half][d] = fire ? 0.0f : m2;
        g_rs[base + (size_t)d*N_ + n] = fire ? 1.0f : 0.0f;
      }
    }
  }
}

// --------------------------------------------------------------------------
extern "C" void kernel_launch(void* const* d_in, const int* in_sizes, int n_in,
                              void* d_out, int out_size)
{
  const float* x       = (const float*)d_in[0];
  const float* q_w     = (const float*)d_in[1];
  const float* q_bn    = (const float*)d_in[2];
  const float* k_w     = (const float*)d_in[3];
  const float* k_bn    = (const float*)d_in[4];
  const float* v_w     = (const float*)d_in[5];
  const float* v_bn    = (const float*)d_in[6];
  const float* proj_w  = (const float*)d_in[7];
  const float* proj_bn = (const float*)d_in[8];
  const float* fc1_w   = (const float*)d_in[9];
  const float* fc1_b   = (const float*)d_in[10];
  const float* fc1_bn  = (const float*)d_in[11];
  const float* fc2_w   = (const float*)d_in[12];
  const float* fc2_b   = (const float*)d_in[13];
  const float* fc2_bn  = (const float*)d_in[14];
  float* out = (float*)d_out;

  const int sp_smem = (int)sizeof(SparseSmem);   // ~76KB
  cudaFuncSetAttribute(spike_gemm_lif_kernel,
      cudaFuncAttributeMaxDynamicSharedMemorySize, sp_smem);

  // prep: transposed weights for the two sparse layers
  prep_wt<<<256, 256>>>(proj_w, 3, C_, C_);
  prep_wt<<<512, 256>>>(fc2_w,  5, C_, H_);

  dim3 blk(128);

  // q, k, v = conv+bn+lif(x) -> binary spikes (dense FFMA2 path)
  qkv_gemm_kernel<<<dim3(N_/32, 6, B_), blk>>>(x, q_w, q_bn, k_w, k_bn, v_w, v_bn);

  // linear attention (q (kT v)) * 0.0625 + attn-LIF -> g_rs
  attn_lif_kernel<<<dim3(B_, 16), dim3(256)>>>();

  // proj conv+bn+lif (SPARSE: input g_rs binary), residual: x1 = x + spike
  spike_gemm_lif_kernel<<<dim3(N_/G_, 1, B_), blk, sp_smem>>>(
      x, nullptr, 3, 4, -1, 3, proj_bn, nullptr, C_);

  // fc1 conv+bn+lif (dense input x1) -> g_h
  gemm_lif_kernel<<<dim3(N_/32, H_/128, B_), blk>>>(
      nullptr, nullptr, nullptr, 4, 5, -2, fc1_w, fc1_bn, fc1_b, C_, H_);

  // fc2 conv+bn+lif (SPARSE: input g_h binary), residual: out = x1 + spike
  spike_gemm_lif_kernel<<<dim3(N_/G_, 1, B_), blk, sp_smem>>>(
      nullptr, out, 5, -1, 4, 5, fc2_bn, fc2_b, H_);
}

// round 16
// speedup vs baseline: 1.1795x; 1.1795x over previous
#include <cuda_runtime.h>
#include <cstddef>
#include <math.h>

#define T_ 4
#define B_ 16
#define C_ 256
#define N_ 512
#define H_ 1024
#define BK 8

// ---------------- scratch (device globals; no allocation allowed) ----------
__device__ __align__(16) float g_qs[(size_t)T_*B_*C_*N_];
__device__ __align__(16) float g_ks[(size_t)T_*B_*C_*N_];
__device__ __align__(16) float g_vs[(size_t)T_*B_*C_*N_];
__device__ __align__(16) float g_rs[(size_t)T_*B_*C_*N_];
__device__ __align__(16) float g_x1[(size_t)T_*B_*C_*N_];
__device__ __align__(16) float g_h [(size_t)T_*B_*H_*N_];

__device__ __forceinline__ float* buf_ptr(int id){
  switch(id){
    case 0: return g_qs; case 1: return g_ks; case 2: return g_vs;
    case 3: return g_rs; case 4: return g_x1; default: return g_h;
  }
}

// ---------------- packed f32x2 helpers (bit-exact per-lane IEEE fma) -------
__device__ __forceinline__ unsigned long long pk2(float v){
  unsigned long long r; unsigned u = __float_as_uint(v);
  asm("mov.b64 %0, {%1, %1};" : "=l"(r) : "r"(u));
  return r;
}
__device__ __forceinline__ void fma2(unsigned long long &d,
                                     unsigned long long a, unsigned long long b){
  asm("fma.rn.f32x2 %0, %1, %2, %0;" : "+l"(d) : "l"(a), "l"(b));
}
__device__ __forceinline__ float2 unpk(unsigned long long p){
  unsigned lo, hi;
  asm("mov.b64 {%0, %1}, %2;" : "=r"(lo), "=r"(hi) : "l"(p));
  return make_float2(__uint_as_float(lo), __uint_as_float(hi));
}

// ------------- fused GEMM + (reference-order) BN + LIF scan over T
// (verbatim R11 best: serial ascending-c fp32 fma per output; FFMA2 pairs
// ADJACENT O-ROWS, b-operand = duplicated X pair -> bit-exact.)
// Block tile 128(o) x 32(n) x 4(t), 128 threads, micro 16x2x4.
#define XROW 320
__device__ __forceinline__ void gemm_lif_body(
    const float* __restrict__ X, float* __restrict__ out,
    const float* __restrict__ res,
    const float* __restrict__ W, const float* __restrict__ bn,
    const float* __restrict__ bias, int Cin, int Cout,
    int b, int o0, int n0)
{
  __shared__ __align__(16) float sW [2][BK][128];
  __shared__ __align__(16) float sX2[2][BK][XROW];
  __shared__ float sBN[4][128];

  const int tid = threadIdx.x;
  const int to = tid >> 4;
  const int tn = tid & 15;
  const int xk = tid >> 4;
  const int xt = (tid >> 2) & 3;
  const int xq = tid & 3;

  {
    const int o = o0 + tid;
    sBN[0][tid] = bn[o] / sqrtf(bn[3*Cout + o] + 1e-5f);
    sBN[1][tid] = bn[2*Cout + o];
    sBN[2][tid] = bn[Cout + o];
    sBN[3][tid] = bias ? bias[o] : 0.0f;
  }

  float4 rw0, rw1, rx0, rx1;
  auto load_regs = [&](int kk){
    const float* wp = W + (size_t)(o0 + tid) * Cin + kk;
    rw0 = *(const float4*)(wp);
    rw1 = *(const float4*)(wp + 4);
    const float* xp = X + ((size_t)(xt*B_ + b) * Cin + kk + xk) * N_ + n0;
    rx0 = *(const float4*)(xp + xq*4);
    rx1 = *(const float4*)(xp + xq*4 + 16);
  };
  auto sts_regs = [&](int s){
    sW[s][0][tid] = rw0.x; sW[s][1][tid] = rw0.y;
    sW[s][2][tid] = rw0.z; sW[s][3][tid] = rw0.w;
    sW[s][4][tid] = rw1.x; sW[s][5][tid] = rw1.y;
    sW[s][6][tid] = rw1.z; sW[s][7][tid] = rw1.w;
    float xv0[4] = {rx0.x, rx0.y, rx0.z, rx0.w};
    float xv1[4] = {rx1.x, rx1.y, rx1.z, rx1.w};
#pragma unroll
    for (int i=0;i<4;i++){
      const int nl = xq*4 + i;
      const int col = (nl>>1)*20 + (nl&1)*8 + xt*2;
      *(unsigned long long*)&sX2[s][xk][col] = pk2(xv0[i]);
    }
#pragma unroll
    for (int i=0;i<4;i++){
      const int nl = xq*4 + 16 + i;
      const int col = (nl>>1)*20 + (nl&1)*8 + xt*2;
      *(unsigned long long*)&sX2[s][xk][col] = pk2(xv1[i]);
    }
  };

  unsigned long long accp[8][8];
#pragma unroll
  for (int i=0;i<8;i++)
#pragma unroll
    for (int j=0;j<8;j++) accp[i][j] = 0ULL;

  auto compute = [&](int s){
#pragma unroll
    for (int k = 0; k < BK; k++){
      const float* wp = &sW[s][k][to*16];
      ulonglong2 w01 = *(const ulonglong2*)(wp);
      ulonglong2 w23 = *(const ulonglong2*)(wp + 4);
      ulonglong2 w45 = *(const ulonglong2*)(wp + 8);
      ulonglong2 w67 = *(const ulonglong2*)(wp + 12);
      unsigned long long ap[8] = {w01.x,w01.y,w23.x,w23.y,
                                  w45.x,w45.y,w67.x,w67.y};
      const float* bp = &sX2[s][k][tn*20];
      ulonglong2 q0 = *(const ulonglong2*)(bp);
      ulonglong2 q1 = *(const ulonglong2*)(bp + 4);
      ulonglong2 q2 = *(const ulonglong2*)(bp + 8);
      ulonglong2 q3 = *(const ulonglong2*)(bp + 12);
      unsigned long long pb[8] = {q0.x,q0.y,q1.x,q1.y,q2.x,q2.y,q3.x,q3.y};
#pragma unroll
      for (int j=0; j<8; j++){
#pragma unroll
        for (int p=0; p<8; p++) fma2(accp[p][j], ap[p], pb[j]);
      }
    }
  };

  const int ntile = Cin / BK;
  load_regs(0);

#pragma unroll 1
  for (int it = 0; it < ntile; it += 2){
    sts_regs(0);
    __syncthreads();
    load_regs((it + 1) * BK);
    compute(0);
    sts_regs(1);
    __syncthreads();
    if (it + 2 < ntile) load_regs((it + 2) * BK);
    compute(1);
  }

#pragma unroll
  for (int p=0; p<8; p++) {
    float accs[2][8];
#pragma unroll
    for (int j=0;j<8;j++){
      float2 pr = unpk(accp[p][j]);
      accs[0][j] = pr.x; accs[1][j] = pr.y;
    }
#pragma unroll
    for (int h2=0; h2<2; h2++) {
      const int oloc = to*16 + 2*p + h2;
      const int o = o0 + oloc;
      const float s_  = sBN[0][oloc];
      const float m_  = sBN[1][oloc];
      const float be_ = sBN[2][oloc];
      const float bc_ = sBN[3][oloc];
#pragma unroll
      for (int n=0; n<2; n++) {
        float mem = 0.0f;
        float sp[4];
#pragma unroll
        for (int t=0; t<4; t++) {
          float ypre = accs[h2][n*4 + t] + bc_;
          float y    = fmaf(ypre - m_, s_, be_);
          float m2   = mem + (y - mem) * 0.5f;
          bool fire  = (m2 > 0.5f);
          mem = fire ? 0.0f : m2;
          sp[t] = fire ? 1.0f : 0.0f;
        }
#pragma unroll
        for (int t=0; t<4; t++) {
          const size_t idx = ((size_t)(t*B_ + b) * Cout + o) * N_ + n0 + tn*2 + n;
          float v = sp[t];
          if (res) v += res[idx];
          out[idx] = v;
        }
      }
    }
  }
}

__global__ __launch_bounds__(128, 2)
void qkv_gemm_kernel(const float* __restrict__ x,
                     const float* __restrict__ Wq, const float* __restrict__ bnq,
                     const float* __restrict__ Wk, const float* __restrict__ bnk,
                     const float* __restrict__ Wv, const float* __restrict__ bnv)
{
  const int gy = blockIdx.y;
  const int gemm = gy >> 1;
  const int o0 = (gy & 1) * 128;
  const float* W  = (gemm == 0) ? Wq  : (gemm == 1) ? Wk  : Wv;
  const float* bn = (gemm == 0) ? bnq : (gemm == 1) ? bnk : bnv;
  float* out = buf_ptr(gemm);
  gemm_lif_body(x, out, nullptr, W, bn, nullptr, C_, C_,
                blockIdx.z, o0, blockIdx.x * 32);
}

__global__ __launch_bounds__(128, 2)
void gemm_lif_kernel(const float* __restrict__ Xext, float* __restrict__ outext,
                     const float* __restrict__ resext,
                     int xid, int oid, int rid,
                     const float* __restrict__ W, const float* __restrict__ bn,
                     const float* __restrict__ bias, int Cin, int Cout)
{
  const float* X   = (xid >= 0) ? buf_ptr(xid) : Xext;
  float* out       = (oid >= 0) ? buf_ptr(oid) : outext;
  const float* res = (rid == -2) ? nullptr : ((rid >= 0) ? buf_ptr(rid) : resext);
  gemm_lif_body(X, out, res, W, bn, bias, Cin, Cout,
                blockIdx.z, blockIdx.y * 128, blockIdx.x * 32);
}

// ------------- spiking linear attention + attn-LIF (bit-exact integer math)
// KV[d1][d2] = sum_m k[d1,m]*v[d2,m] via ballot-bitpack + popc (spikes binary)
// r = 0.0625 * q @ KV ; LIF over t (dyadic-exact).
// R15: 512 threads (thread-per-n), mem[16] only -> low regs, high occupancy.
__global__ __launch_bounds__(512, 2)
void attn_lif_kernel()
{
  __shared__ unsigned kb[16][17], vb[16][17];
  __shared__ float sKV[16][17];
  const int b = blockIdx.x;
  const int h = blockIdx.y;
  const int tid = threadIdx.x;            // = n (0..511)
  const int warp = tid >> 5, lane = tid & 31;   // 16 warps

  float mem[16];
#pragma unroll
  for (int d=0; d<16; d++) mem[d] = 0.0f;

#pragma unroll 1
  for (int t=0; t<T_; t++){
    const size_t base = ((size_t)(t*B_ + b) * C_ + h*16) * N_;
    __syncthreads();   // prior iteration done reading kb/vb/sKV

    // bitpack k,v: 256 (row,word) pairs over 16 warps -> 16 each
#pragma unroll 4
    for (int i = 0; i < 16; i++){
      const int idx = warp * 16 + i;        // 0..255
      const int row = idx >> 4, word = idx & 15;
      const size_t off = base + (size_t)row * N_ + word * 32 + lane;
      unsigned uk = __ballot_sync(0xffffffffu, g_ks[off] != 0.0f);
      unsigned uv = __ballot_sync(0xffffffffu, g_vs[off] != 0.0f);
      if (lane == 0){ kb[row][word] = uk; vb[row][word] = uv; }
    }
    __syncthreads();

    // KV via popc (exact integers): threads 0..255 each own one (d1,d2)
    if (tid < 256){
      const int d1 = tid >> 4, d2 = tid & 15;
      int kv = 0;
#pragma unroll
      for (int w=0; w<16; w++) kv += __popc(kb[d1][w] & vb[d2][w]);
      sKV[d1][d2] = (float)kv;
    }
    __syncthreads();

    // r = q @ KV, scaled, then attn-LIF (all dyadic-exact); n = tid
    {
      const int n = tid;
      float qv[16];
#pragma unroll
      for (int dd=0; dd<16; dd++) qv[dd] = g_qs[base + (size_t)dd*N_ + n];
#pragma unroll
      for (int d=0; d<16; d++){
        float r = 0.0f;
#pragma unroll
        for (int dd=0; dd<16; dd++) r = fmaf(qv[dd], sKV[dd][d], r);
        r *= 0.0625f;   // SCALE * SCALE (exact)
        float m2 = mem[d] + (r - mem[d]) * 0.5f;
        bool fire = (m2 > 0.5f);
        mem[d] = fire ? 0.0f : m2;
        g_rs[base + (size_t)d*N_ + n] = fire ? 1.0f : 0.0f;
      }
    }
  }
}

// --------------------------------------------------------------------------
extern "C" void kernel_launch(void* const* d_in, const int* in_sizes, int n_in,
                              void* d_out, int out_size)
{
  const float* x       = (const float*)d_in[0];
  const float* q_w     = (const float*)d_in[1];
  const float* q_bn    = (const float*)d_in[2];
  const float* k_w     = (const float*)d_in[3];
  const float* k_bn    = (const float*)d_in[4];
  const float* v_w     = (const float*)d_in[5];
  const float* v_bn    = (const float*)d_in[6];
  const float* proj_w  = (const float*)d_in[7];
  const float* proj_bn = (const float*)d_in[8];
  const float* fc1_w   = (const float*)d_in[9];
  const float* fc1_b   = (const float*)d_in[10];
  const float* fc1_bn  = (const float*)d_in[11];
  const float* fc2_w   = (const float*)d_in[12];
  const float* fc2_b   = (const float*)d_in[13];
  const float* fc2_bn  = (const float*)d_in[14];
  float* out = (float*)d_out;

  dim3 blk(128);

  // q, k, v = conv+bn+lif(x) -> binary spikes (one fused launch, t in-register)
  qkv_gemm_kernel<<<dim3(N_/32, 6, B_), blk>>>(x, q_w, q_bn, k_w, k_bn, v_w, v_bn);

  // linear attention (q (kT v)) * 0.0625 + attn-LIF -> g_rs
  attn_lif_kernel<<<dim3(B_, 16), dim3(512)>>>();

  // proj conv+bn+lif, fused residual: x1 = x + spike
  gemm_lif_kernel<<<dim3(N_/32, C_/128, B_), blk>>>(nullptr, nullptr, x, 3, 4, -1,
                                                    proj_w, proj_bn, nullptr, C_, C_);

  // fc1 conv+bn+lif -> g_h (Cout=1024)
  gemm_lif_kernel<<<dim3(N_/32, H_/128, B_), blk>>>(nullptr, nullptr, nullptr, 4, 5, -2,
                                                    fc1_w, fc1_bn, fc1_b, C_, H_);

  // fc2 conv+bn+lif, fused residual: out = x1 + spike (Cin=1024)
  gemm_lif_kernel<<<dim3(N_/32, C_/128, B_), blk>>>(nullptr, out, nullptr, 5, -1, 4,
                                                    fc2_w, fc2_bn, fc2_b, H_, C_);
}

// round 17
// speedup vs baseline: 1.8588x; 1.5759x over previous
#include <cuda_runtime.h>
#include <cstddef>
#include <math.h>

#define T_ 4
#define B_ 16
#define C_ 256
#define N_ 512
#define H_ 1024
#define BK 8

// ---------------- scratch (device globals; no allocation allowed) ----------
__device__ __align__(16) float g_qs[(size_t)T_*B_*C_*N_];
__device__ __align__(16) float g_ks[(size_t)T_*B_*C_*N_];
__device__ __align__(16) float g_vs[(size_t)T_*B_*C_*N_];
__device__ __align__(16) float g_rs[(size_t)T_*B_*C_*N_];
__device__ __align__(16) float g_x1[(size_t)T_*B_*C_*N_];
__device__ __align__(16) float g_h [(size_t)T_*B_*H_*N_];

__device__ __forceinline__ float* buf_ptr(int id){
  switch(id){
    case 0: return g_qs; case 1: return g_ks; case 2: return g_vs;
    case 3: return g_rs; case 4: return g_x1; default: return g_h;
  }
}

// ---------------- packed f32x2 helpers (bit-exact per-lane IEEE fma) -------
__device__ __forceinline__ unsigned long long pk2(float v){
  unsigned long long r; unsigned u = __float_as_uint(v);
  asm("mov.b64 %0, {%1, %1};" : "=l"(r) : "r"(u));
  return r;
}
__device__ __forceinline__ void fma2(unsigned long long &d,
                                     unsigned long long a, unsigned long long b){
  asm("fma.rn.f32x2 %0, %1, %2, %0;" : "+l"(d) : "l"(a), "l"(b));
}
__device__ __forceinline__ float2 unpk(unsigned long long p){
  unsigned lo, hi;
  asm("mov.b64 {%0, %1}, %2;" : "=r"(lo), "=r"(hi) : "l"(p));
  return make_float2(__uint_as_float(lo), __uint_as_float(hi));
}

// ------------- fused GEMM + (reference-order) BN + LIF scan over T
// (verbatim R11 best: serial ascending-c fp32 fma per output; FFMA2 pairs
// ADJACENT O-ROWS, b-operand = duplicated X pair -> bit-exact.)
// Block tile 128(o) x 32(n) x 4(t), 128 threads, micro 16x2x4.
#define XROW 320
__device__ __forceinline__ void gemm_lif_body(
    const float* __restrict__ X, float* __restrict__ out,
    const float* __restrict__ res,
    const float* __restrict__ W, const float* __restrict__ bn,
    const float* __restrict__ bias, int Cin, int Cout,
    int b, int o0, int n0)
{
  __shared__ __align__(16) float sW [2][BK][128];
  __shared__ __align__(16) float sX2[2][BK][XROW];
  __shared__ float sBN[4][128];

  const int tid = threadIdx.x;
  const int to = tid >> 4;
  const int tn = tid & 15;
  const int xk = tid >> 4;
  const int xt = (tid >> 2) & 3;
  const int xq = tid & 3;

  {
    const int o = o0 + tid;
    sBN[0][tid] = bn[o] / sqrtf(bn[3*Cout + o] + 1e-5f);
    sBN[1][tid] = bn[2*Cout + o];
    sBN[2][tid] = bn[Cout + o];
    sBN[3][tid] = bias ? bias[o] : 0.0f;
  }

  float4 rw0, rw1, rx0, rx1;
  auto load_regs = [&](int kk){
    const float* wp = W + (size_t)(o0 + tid) * Cin + kk;
    rw0 = *(const float4*)(wp);
    rw1 = *(const float4*)(wp + 4);
    const float* xp = X + ((size_t)(xt*B_ + b) * Cin + kk + xk) * N_ + n0;
    rx0 = *(const float4*)(xp + xq*4);
    rx1 = *(const float4*)(xp + xq*4 + 16);
  };
  auto sts_regs = [&](int s){
    sW[s][0][tid] = rw0.x; sW[s][1][tid] = rw0.y;
    sW[s][2][tid] = rw0.z; sW[s][3][tid] = rw0.w;
    sW[s][4][tid] = rw1.x; sW[s][5][tid] = rw1.y;
    sW[s][6][tid] = rw1.z; sW[s][7][tid] = rw1.w;
    float xv0[4] = {rx0.x, rx0.y, rx0.z, rx0.w};
    float xv1[4] = {rx1.x, rx1.y, rx1.z, rx1.w};
#pragma unroll
    for (int i=0;i<4;i++){
      const int nl = xq*4 + i;
      const int col = (nl>>1)*20 + (nl&1)*8 + xt*2;
      *(unsigned long long*)&sX2[s][xk][col] = pk2(xv0[i]);
    }
#pragma unroll
    for (int i=0;i<4;i++){
      const int nl = xq*4 + 16 + i;
      const int col = (nl>>1)*20 + (nl&1)*8 + xt*2;
      *(unsigned long long*)&sX2[s][xk][col] = pk2(xv1[i]);
    }
  };

  unsigned long long accp[8][8];
#pragma unroll
  for (int i=0;i<8;i++)
#pragma unroll
    for (int j=0;j<8;j++) accp[i][j] = 0ULL;

  auto compute = [&](int s){
#pragma unroll
    for (int k = 0; k < BK; k++){
      const float* wp = &sW[s][k][to*16];
      ulonglong2 w01 = *(const ulonglong2*)(wp);
      ulonglong2 w23 = *(const ulonglong2*)(wp + 4);
      ulonglong2 w45 = *(const ulonglong2*)(wp + 8);
      ulonglong2 w67 = *(const ulonglong2*)(wp + 12);
      unsigned long long ap[8] = {w01.x,w01.y,w23.x,w23.y,
                                  w45.x,w45.y,w67.x,w67.y};
      const float* bp = &sX2[s][k][tn*20];
      ulonglong2 q0 = *(const ulonglong2*)(bp);
      ulonglong2 q1 = *(const ulonglong2*)(bp + 4);
      ulonglong2 q2 = *(const ulonglong2*)(bp + 8);
      ulonglong2 q3 = *(const ulonglong2*)(bp + 12);
      unsigned long long pb[8] = {q0.x,q0.y,q1.x,q1.y,q2.x,q2.y,q3.x,q3.y};
#pragma unroll
      for (int j=0; j<8; j++){
#pragma unroll
        for (int p=0; p<8; p++) fma2(accp[p][j], ap[p], pb[j]);
      }
    }
  };

  const int ntile = Cin / BK;
  load_regs(0);

#pragma unroll 1
  for (int it = 0; it < ntile; it += 2){
    sts_regs(0);
    __syncthreads();
    load_regs((it + 1) * BK);
    compute(0);
    sts_regs(1);
    __syncthreads();
    if (it + 2 < ntile) load_regs((it + 2) * BK);
    compute(1);
  }

#pragma unroll
  for (int p=0; p<8; p++) {
    float accs[2][8];
#pragma unroll
    for (int j=0;j<8;j++){
      float2 pr = unpk(accp[p][j]);
      accs[0][j] = pr.x; accs[1][j] = pr.y;
    }
#pragma unroll
    for (int h2=0; h2<2; h2++) {
      const int oloc = to*16 + 2*p + h2;
      const int o = o0 + oloc;
      const float s_  = sBN[0][oloc];
      const float m_  = sBN[1][oloc];
      const float be_ = sBN[2][oloc];
      const float bc_ = sBN[3][oloc];
#pragma unroll
      for (int n=0; n<2; n++) {
        float mem = 0.0f;
        float sp[4];
#pragma unroll
        for (int t=0; t<4; t++) {
          float ypre = accs[h2][n*4 + t] + bc_;
          float y    = fmaf(ypre - m_, s_, be_);
          float m2   = mem + (y - mem) * 0.5f;
          bool fire  = (m2 > 0.5f);
          mem = fire ? 0.0f : m2;
          sp[t] = fire ? 1.0f : 0.0f;
        }
#pragma unroll
        for (int t=0; t<4; t++) {
          const size_t idx = ((size_t)(t*B_ + b) * Cout + o) * N_ + n0 + tn*2 + n;
          float v = sp[t];
          if (res) v += res[idx];
          out[idx] = v;
        }
      }
    }
  }
}

__global__ __launch_bounds__(128, 2)
void qkv_gemm_kernel(const float* __restrict__ x,
                     const float* __restrict__ Wq, const float* __restrict__ bnq,
                     const float* __restrict__ Wk, const float* __restrict__ bnk,
                     const float* __restrict__ Wv, const float* __restrict__ bnv)
{
  const int gy = blockIdx.y;
  const int gemm = gy >> 1;
  const int o0 = (gy & 1) * 128;
  const float* W  = (gemm == 0) ? Wq  : (gemm == 1) ? Wk  : Wv;
  const float* bn = (gemm == 0) ? bnq : (gemm == 1) ? bnk : bnv;
  float* out = buf_ptr(gemm);
  gemm_lif_body(x, out, nullptr, W, bn, nullptr, C_, C_,
                blockIdx.z, o0, blockIdx.x * 32);
}

__global__ __launch_bounds__(128, 2)
void gemm_lif_kernel(const float* __restrict__ Xext, float* __restrict__ outext,
                     const float* __restrict__ resext,
                     int xid, int oid, int rid,
                     const float* __restrict__ W, const float* __restrict__ bn,
                     const float* __restrict__ bias, int Cin, int Cout)
{
  const float* X   = (xid >= 0) ? buf_ptr(xid) : Xext;
  float* out       = (oid >= 0) ? buf_ptr(oid) : outext;
  const float* res = (rid == -2) ? nullptr : ((rid >= 0) ? buf_ptr(rid) : resext);
  gemm_lif_body(X, out, res, W, bn, bias, Cin, Cout,
                blockIdx.z, blockIdx.y * 128, blockIdx.x * 32);
}

// ------------- spiking linear attention + attn-LIF (bit-exact integer math)
// KV[d1][d2] = sum_m k[d1,m]*v[d2,m] via ballot-bitpack + popc (spikes binary)
// r = 0.0625 * q @ KV ; LIF over t (dyadic-exact).
// 512 threads (thread-per-n), mem[16] only -> low regs, high occupancy.
__global__ __launch_bounds__(512, 2)
void attn_lif_kernel()
{
  __shared__ unsigned kb[16][17], vb[16][17];
  __shared__ float sKV[16][17];
  const int b = blockIdx.x;
  const int h = blockIdx.y;
  const int tid = threadIdx.x;            // = n (0..511)
  const int warp = tid >> 5, lane = tid & 31;   // 16 warps

  float mem[16];
#pragma unroll
  for (int d=0; d<16; d++) mem[d] = 0.0f;

#pragma unroll 1
  for (int t=0; t<T_; t++){
    const size_t base = ((size_t)(t*B_ + b) * C_ + h*16) * N_;
    __syncthreads();   // prior iteration done reading kb/vb/sKV

    // bitpack k,v: 256 (row,word) pairs over 16 warps -> 16 each
#pragma unroll 4
    for (int i = 0; i < 16; i++){
      const int idx = warp * 16 + i;        // 0..255
      const int row = idx >> 4, word = idx & 15;
      const size_t off = base + (size_t)row * N_ + word * 32 + lane;
      unsigned uk = __ballot_sync(0xffffffffu, g_ks[off] != 0.0f);
      unsigned uv = __ballot_sync(0xffffffffu, g_vs[off] != 0.0f);
      if (lane == 0){ kb[row][word] = uk; vb[row][word] = uv; }
    }
    __syncthreads();

    // KV via popc (exact integers): threads 0..255 each own one (d1,d2)
    if (tid < 256){
      const int d1 = tid >> 4, d2 = tid & 15;
      int kv = 0;
#pragma unroll
      for (int w=0; w<16; w++) kv += __popc(kb[d1][w] & vb[d2][w]);
      sKV[d1][d2] = (float)kv;
    }
    __syncthreads();

    // r = q @ KV, scaled, then attn-LIF (all dyadic-exact); n = tid
    {
      const int n = tid;
      float qv[16];
#pragma unroll
      for (int dd=0; dd<16; dd++) qv[dd] = g_qs[base + (size_t)dd*N_ + n];
#pragma unroll
      for (int d=0; d<16; d++){
        float r = 0.0f;
#pragma unroll
        for (int dd=0; dd<16; dd++) r = fmaf(qv[dd], sKV[dd][d], r);
        r *= 0.0625f;   // SCALE * SCALE (exact)
        float m2 = mem[d] + (r - mem[d]) * 0.5f;
        bool fire = (m2 > 0.5f);
        mem[d] = fire ? 0.0f : m2;
        g_rs[base + (size_t)d*N_ + n] = fire ? 1.0f : 0.0f;
      }
    }
  }
}

// --------------------------------------------------------------------------
extern "C" void kernel_launch(void* const* d_in, const int* in_sizes, int n_in,
                              void* d_out, int out_size)
{
  const float* x       = (const float*)d_in[0];
  const float* q_w     = (const float*)d_in[1];
  const float* q_bn    = (const float*)d_in[2];
  const float* k_w     = (const float*)d_in[3];
  const float* k_bn    = (const float*)d_in[4];
  const float* v_w     = (const float*)d_in[5];
  const float* v_bn    = (const float*)d_in[6];
  const float* proj_w  = (const float*)d_in[7];
  const float* proj_bn = (const float*)d_in[8];
  const float* fc1_w   = (const float*)d_in[9];
  const float* fc1_b   = (const float*)d_in[10];
  const float* fc1_bn  = (const float*)d_in[11];
  const float* fc2_w   = (const float*)d_in[12];
  const float* fc2_b   = (const float*)d_in[13];
  const float* fc2_bn  = (const float*)d_in[14];
  float* out = (float*)d_out;

  dim3 blk(128);

  // q, k, v = conv+bn+lif(x) -> binary spikes (one fused launch, t in-register)
  qkv_gemm_kernel<<<dim3(N_/32, 6, B_), blk>>>(x, q_w, q_bn, k_w, k_bn, v_w, v_bn);

  // linear attention (q (kT v)) * 0.0625 + attn-LIF -> g_rs
  attn_lif_kernel<<<dim3(B_, 16), dim3(512)>>>();

  // proj conv+bn+lif, fused residual: x1 = x + spike
  gemm_lif_kernel<<<dim3(N_/32, C_/128, B_), blk>>>(nullptr, nullptr, x, 3, 4, -1,
                                                    proj_w, proj_bn, nullptr, C_, C_);

  // fc1 conv+bn+lif -> g_h (Cout=1024)
  gemm_lif_kernel<<<dim3(N_/32, H_/128, B_), blk>>>(nullptr, nullptr, nullptr, 4, 5, -2,
                                                    fc1_w, fc1_bn, fc1_b, C_, H_);

  // fc2 conv+bn+lif, fused residual: out = x1 + spike (Cin=1024)
  gemm_lif_kernel<<<dim3(N_/32, C_/128, B_), blk>>>(nullptr, out, nullptr, 5, -1, 4,
                                                    fc2_w, fc2_bn, fc2_b, H_, C_);
}